// round 3
// baseline (speedup 1.0000x reference)
#include <cuda_runtime.h>

// GMP forward:
// out[b,j] = sum_{i=0..7} xc[b, j+i-7] * F_i(j+i-7)
// F_i(n)   = W[i,0] + sum_{m=0..7} sum_{d=0..2} W[i,1+3m+d] * a(n+m-7)^(d+1)
// xc zero-extended for n<0; a(n)=|xc(n)| zero-extended.

constexpr int Bn  = 64;
constexpr int Tn  = 16384;
constexpr int Mm  = 8;
constexpr int CH  = 8;     // samples per thread
constexpr int TPB = 128;

__global__ __launch_bounds__(TPB)
void gmp_kernel(const float2* __restrict__ x,     // (B,T) complex as float2
                const float*  __restrict__ W,     // (8,25)
                float2*       __restrict__ out)   // (B,T) complex as float2
{
    __shared__ float sW[Mm * 25];
    for (int q = threadIdx.x; q < Mm * 25; q += TPB) sW[q] = W[q];
    __syncthreads();

    const int per_row = Tn / CH;                       // 2048
    const int idx = blockIdx.x * TPB + threadIdx.x;    // < B*per_row
    const int b   = idx / per_row;
    const int j0  = (idx - b * per_row) * CH;

    const float2* xrow = x + (size_t)b * Tn;

    // Load complex window: array index k corresponds to n = j0 + k - 14.
    float xr[CH + 14], xi[CH + 14];
#pragma unroll
    for (int k = 0; k < CH + 14; k++) {
        const int n = j0 + k - 14;
        float2 v;
        if (n >= 0) v = xrow[n];
        else        v = make_float2(0.f, 0.f);
        xr[k] = v.x; xi[k] = v.y;
    }

    // Envelope powers a^1, a^2, a^3 over the window.
    float a1[CH + 14], a2[CH + 14], a3[CH + 14];
#pragma unroll
    for (int k = 0; k < CH + 14; k++) {
        const float m2 = fmaf(xr[k], xr[k], xi[k] * xi[k]);
        const float a  = sqrtf(m2);
        a1[k] = a; a2[k] = m2; a3[k] = a * m2;
    }

    float or_[CH], oi_[CH];
#pragma unroll
    for (int c = 0; c < CH; c++) { or_[c] = 0.f; oi_[c] = 0.f; }

#pragma unroll
    for (int i = 0; i < Mm; i++) {
        const float w0 = sW[i * 25];
        float wd[24];
#pragma unroll
        for (int q = 0; q < 24; q++) wd[q] = sW[i * 25 + 1 + q];

#pragma unroll
        for (int c = 0; c < CH; c++) {
            float F = w0;
#pragma unroll
            for (int m = 0; m < Mm; m++) {
                const int t = c + i + m;      // a-index for n = j0+c+i+m-14
                F = fmaf(wd[m * 3 + 0], a1[t], F);
                F = fmaf(wd[m * 3 + 1], a2[t], F);
                F = fmaf(wd[m * 3 + 2], a3[t], F);
            }
            const int xk = c + i + 7;         // x-index for n = j0+c+i-7
            or_[c] = fmaf(xr[xk], F, or_[c]);
            oi_[c] = fmaf(xi[xk], F, oi_[c]);
        }
    }

    float2* orow = out + (size_t)b * Tn + j0;
#pragma unroll
    for (int c = 0; c < CH; c++) orow[c] = make_float2(or_[c], oi_[c]);
}

extern "C" void kernel_launch(void* const* d_in, const int* in_sizes, int n_in,
                              void* d_out, int out_size)
{
    const float2* x = (const float2*)d_in[0];
    // d_in[1] = h_0 (unused)
    const float*  W = (const float*)d_in[2];
    float2* out = (float2*)d_out;

    const int total_threads = Bn * (Tn / CH);      // 131072
    const int grid = total_threads / TPB;          // 1024
    gmp_kernel<<<grid, TPB>>>(x, W, out);
}

// round 4
// speedup vs baseline: 1.4827x; 1.4827x over previous
#include <cuda_runtime.h>

// GMP forward:
// out[b,j] = sum_{i=0..7} xc[b, j+i-7] * F_i(j+i-7)
// F_i(n)   = W[i,0] + sum_{m=0..7} sum_{d=0..2} W[i,1+3m+d] * a(n+m-7)^(d+1)
// xc zero-extended for n<0; a(n)=|xc(n)| zero-extended.

constexpr int Bn  = 64;
constexpr int Tn  = 16384;
constexpr int Mm  = 8;
constexpr int CH  = 8;     // samples per thread
constexpr int TPB = 128;

__global__ __launch_bounds__(TPB)
void gmp_kernel(const float2* __restrict__ x,     // (B,T) complex as float2
                const float*  __restrict__ W,     // (8,25)
                float2*       __restrict__ out)   // (B,T) complex as float2
{
    __shared__ float sW[Mm * 25];
    for (int q = threadIdx.x; q < Mm * 25; q += TPB) sW[q] = W[q];
    __syncthreads();

    const int per_row = Tn / CH;                       // 2048
    const int idx = blockIdx.x * TPB + threadIdx.x;    // < B*per_row
    const int b   = idx / per_row;
    const int j0  = (idx - b * per_row) * CH;

    const float2* xrow = x + (size_t)b * Tn;

    // Load complex window: array index k corresponds to n = j0 + k - 14.
    float xr[CH + 14], xi[CH + 14];
#pragma unroll
    for (int k = 0; k < CH + 14; k++) {
        const int n = j0 + k - 14;
        float2 v;
        if (n >= 0) v = xrow[n];
        else        v = make_float2(0.f, 0.f);
        xr[k] = v.x; xi[k] = v.y;
    }

    // Envelope powers a^1, a^2, a^3 over the window.
    float a1[CH + 14], a2[CH + 14], a3[CH + 14];
#pragma unroll
    for (int k = 0; k < CH + 14; k++) {
        const float m2 = fmaf(xr[k], xr[k], xi[k] * xi[k]);
        const float a  = sqrtf(m2);
        a1[k] = a; a2[k] = m2; a3[k] = a * m2;
    }

    float or_[CH], oi_[CH];
#pragma unroll
    for (int c = 0; c < CH; c++) { or_[c] = 0.f; oi_[c] = 0.f; }

#pragma unroll
    for (int i = 0; i < Mm; i++) {
        const float w0 = sW[i * 25];
        float wd[24];
#pragma unroll
        for (int q = 0; q < 24; q++) wd[q] = sW[i * 25 + 1 + q];

#pragma unroll
        for (int c = 0; c < CH; c++) {
            float F = w0;
#pragma unroll
            for (int m = 0; m < Mm; m++) {
                const int t = c + i + m;      // a-index for n = j0+c+i+m-14
                F = fmaf(wd[m * 3 + 0], a1[t], F);
                F = fmaf(wd[m * 3 + 1], a2[t], F);
                F = fmaf(wd[m * 3 + 2], a3[t], F);
            }
            const int xk = c + i + 7;         // x-index for n = j0+c+i-7
            or_[c] = fmaf(xr[xk], F, or_[c]);
            oi_[c] = fmaf(xi[xk], F, oi_[c]);
        }
    }

    float2* orow = out + (size_t)b * Tn + j0;
#pragma unroll
    for (int c = 0; c < CH; c++) orow[c] = make_float2(or_[c], oi_[c]);
}

extern "C" void kernel_launch(void* const* d_in, const int* in_sizes, int n_in,
                              void* d_out, int out_size)
{
    const float2* x = (const float2*)d_in[0];
    // d_in[1] = h_0 (unused)
    const float*  W = (const float*)d_in[2];
    float2* out = (float2*)d_out;

    const int total_threads = Bn * (Tn / CH);      // 131072
    const int grid = total_threads / TPB;          // 1024
    gmp_kernel<<<grid, TPB>>>(x, W, out);
}

// round 5
// speedup vs baseline: 1.4985x; 1.0107x over previous
#include <cuda_runtime.h>

// GMP forward:
// out[b,j] = sum_{i=0..7} xc[b, j+i-7] * F_i(j+i-7)
// F_i(n)   = W[i,0] + sum_{m=0..7} sum_{d=0..2} W[i,1+3m+d] * a(n+m-7)^(d+1)
// xc zero-extended for n<0; a(n)=|xc(n)| zero-extended.

constexpr int Bn  = 64;
constexpr int Tn  = 16384;
constexpr int Mm  = 8;
constexpr int CH  = 8;     // samples per thread
constexpr int TPB = 128;

__global__ __launch_bounds__(TPB)
void gmp_kernel(const float2* __restrict__ x,     // (B,T) complex as float2
                const float*  __restrict__ W,     // (8,25)
                float2*       __restrict__ out)   // (B,T) complex as float2
{
    __shared__ float sW[Mm * 25];
    for (int q = threadIdx.x; q < Mm * 25; q += TPB) sW[q] = W[q];
    __syncthreads();

    const int per_row = Tn / CH;                       // 2048
    const int idx = blockIdx.x * TPB + threadIdx.x;    // < B*per_row
    const int b   = idx / per_row;
    const int j0  = (idx - b * per_row) * CH;

    const float2* xrow = x + (size_t)b * Tn;

    // Load complex window: array index k corresponds to n = j0 + k - 14.
    float xr[CH + 14], xi[CH + 14];
#pragma unroll
    for (int k = 0; k < CH + 14; k++) {
        const int n = j0 + k - 14;
        float2 v;
        if (n >= 0) v = xrow[n];
        else        v = make_float2(0.f, 0.f);
        xr[k] = v.x; xi[k] = v.y;
    }

    // Envelope powers a^1, a^2, a^3 over the window.
    float a1[CH + 14], a2[CH + 14], a3[CH + 14];
#pragma unroll
    for (int k = 0; k < CH + 14; k++) {
        const float m2 = fmaf(xr[k], xr[k], xi[k] * xi[k]);
        const float a  = sqrtf(m2);
        a1[k] = a; a2[k] = m2; a3[k] = a * m2;
    }

    float or_[CH], oi_[CH];
#pragma unroll
    for (int c = 0; c < CH; c++) { or_[c] = 0.f; oi_[c] = 0.f; }

#pragma unroll
    for (int i = 0; i < Mm; i++) {
        const float w0 = sW[i * 25];
        float wd[24];
#pragma unroll
        for (int q = 0; q < 24; q++) wd[q] = sW[i * 25 + 1 + q];

#pragma unroll
        for (int c = 0; c < CH; c++) {
            float F = w0;
#pragma unroll
            for (int m = 0; m < Mm; m++) {
                const int t = c + i + m;      // a-index for n = j0+c+i+m-14
                F = fmaf(wd[m * 3 + 0], a1[t], F);
                F = fmaf(wd[m * 3 + 1], a2[t], F);
                F = fmaf(wd[m * 3 + 2], a3[t], F);
            }
            const int xk = c + i + 7;         // x-index for n = j0+c+i-7
            or_[c] = fmaf(xr[xk], F, or_[c]);
            oi_[c] = fmaf(xi[xk], F, oi_[c]);
        }
    }

    float2* orow = out + (size_t)b * Tn + j0;
#pragma unroll
    for (int c = 0; c < CH; c++) orow[c] = make_float2(or_[c], oi_[c]);
}

extern "C" void kernel_launch(void* const* d_in, const int* in_sizes, int n_in,
                              void* d_out, int out_size)
{
    const float2* x = (const float2*)d_in[0];
    // d_in[1] = h_0 (unused)
    const float*  W = (const float*)d_in[2];
    float2* out = (float2*)d_out;

    const int total_threads = Bn * (Tn / CH);      // 131072
    const int grid = total_threads / TPB;          // 1024
    gmp_kernel<<<grid, TPB>>>(x, W, out);
}